// round 2
// baseline (speedup 1.0000x reference)
#include <cuda_runtime.h>

#define Bv 2
#define Cv 64
#define Nv 1024
#define Ev 32
#define TI 8   // i-rows per block in edge kernel

// Scratch for projected node features t1, t2: (B*E, N) each. 256 KB each.
__device__ float g_t1[Bv * Ev * Nv];
__device__ float g_t2[Bv * Ev * Nv];

// ---------------------------------------------------------------------------
// Kernel 1: t[b,e,n] = sum_c th12[e,c] * emb[b,c,n], for both weight sets.
// ---------------------------------------------------------------------------
__global__ void proj_kernel(const float* __restrict__ emb,
                            const float* __restrict__ th12_1,
                            const float* __restrict__ th12_2) {
    const int be = blockIdx.x;          // 0..B*E-1
    const int b  = be / Ev;
    const int e  = be % Ev;
    const int n  = blockIdx.y * blockDim.x + threadIdx.x;

    __shared__ float w1[Cv];
    __shared__ float w2[Cv];
    if (threadIdx.x < Cv) {
        w1[threadIdx.x] = th12_1[e * Cv + threadIdx.x];
        w2[threadIdx.x] = th12_2[e * Cv + threadIdx.x];
    }
    __syncthreads();

    const float* ebase = emb + (size_t)b * Cv * Nv + n;
    float s1 = 0.0f, s2 = 0.0f;
#pragma unroll 16
    for (int c = 0; c < Cv; ++c) {
        float x = ebase[(size_t)c * Nv];   // coalesced
        s1 = fmaf(w1[c], x, s1);
        s2 = fmaf(w2[c], x, s2);
    }
    g_t1[be * Nv + n] = s1;
    g_t2[be * Nv + n] = s2;
}

// ---------------------------------------------------------------------------
// Kernel 2: out[b,e,i,j] = relu(2*max(t1_i,t1_j) + a5*dij)
//                        * sigmoid(relu(2*max(t2_i,t2_j) + g5*dij))
// NOTE: the reference applies relu INSIDE _node2edge for both paths, so the
// gate's sigmoid argument is relu'd too (gate in [0.5, 1)).
// Grid: (N/TI, B*E). Block 256 threads; each thread owns 4 consecutive j.
// tj vectors are loaded once and reused across TI output rows -> L2 read
// traffic cut by TI, leaving pure HBM-store-bound.
// ---------------------------------------------------------------------------
__device__ __forceinline__ float gate_sig(float x) {
    // sigmoid(relu(x))
    float xr = fmaxf(x, 0.0f);
    return __fdividef(1.0f, 1.0f + __expf(-xr));
}

__global__ void __launch_bounds__(256) edge_kernel(
    const float* __restrict__ th5_1,
    const float* __restrict__ th5_2,
    float* __restrict__ out) {
    const int i0 = blockIdx.x * TI;     // first i-row of this block
    const int be = blockIdx.y;          // 0..B*E-1
    const int e  = be % Ev;

    const float* __restrict__ r1 = g_t1 + be * Nv;
    const float* __restrict__ r2 = g_t2 + be * Nv;

    const float a5 = th5_1[e];
    const float g5 = th5_2[e];

    const int j0 = threadIdx.x * 4;
    const float4 tj1 = *reinterpret_cast<const float4*>(r1 + j0);
    const float4 tj2 = *reinterpret_cast<const float4*>(r2 + j0);

    float* dst = out + (((size_t)be * Nv) + i0) * Nv + j0;

#pragma unroll
    for (int r = 0; r < TI; ++r) {
        const int i = i0 + r;
        const float ti1 = r1[i];        // uniform broadcast load (L1/L2 hit)
        const float ti2 = r2[i];

        float4 o;
        {
            float d = (j0 + 0 == i) ? 1.0f : 0.0f;
            float a = fmaxf(2.0f * fmaxf(ti1, tj1.x) + a5 * d, 0.0f);
            o.x = a * gate_sig(2.0f * fmaxf(ti2, tj2.x) + g5 * d);
        }
        {
            float d = (j0 + 1 == i) ? 1.0f : 0.0f;
            float a = fmaxf(2.0f * fmaxf(ti1, tj1.y) + a5 * d, 0.0f);
            o.y = a * gate_sig(2.0f * fmaxf(ti2, tj2.y) + g5 * d);
        }
        {
            float d = (j0 + 2 == i) ? 1.0f : 0.0f;
            float a = fmaxf(2.0f * fmaxf(ti1, tj1.z) + a5 * d, 0.0f);
            o.z = a * gate_sig(2.0f * fmaxf(ti2, tj2.z) + g5 * d);
        }
        {
            float d = (j0 + 3 == i) ? 1.0f : 0.0f;
            float a = fmaxf(2.0f * fmaxf(ti1, tj1.w) + a5 * d, 0.0f);
            o.w = a * gate_sig(2.0f * fmaxf(ti2, tj2.w) + g5 * d);
        }

        *reinterpret_cast<float4*>(dst) = o;
        dst += Nv;                      // next i-row
    }
}

// ---------------------------------------------------------------------------
// Launch. Resolve input indices defensively from in_sizes:
//   dict order:   sizes [BCN, EC, EC, E, EC, EC, E] -> th5 at 3 and 6
//   sorted order: sizes [BCN, EC, EC, EC, EC, E, E] -> th5 at 5 and 6
// ---------------------------------------------------------------------------
extern "C" void kernel_launch(void* const* d_in, const int* in_sizes, int n_in,
                              void* d_out, int out_size) {
    const float* emb = (const float*)d_in[0];
    const float *th12_1, *th5_1, *th12_2, *th5_2;

    if (n_in >= 7 && in_sizes[3] == Ev) {
        // insertion (dict) order: emb, th12_1, th34_1, th5_1, th12_2, th34_2, th5_2
        th12_1 = (const float*)d_in[1];
        th5_1  = (const float*)d_in[3];
        th12_2 = (const float*)d_in[4];
        th5_2  = (const float*)d_in[6];
    } else {
        // alphabetical order: emb, th12_1, th12_2, th34_1, th34_2, th5_1, th5_2
        th12_1 = (const float*)d_in[1];
        th12_2 = (const float*)d_in[2];
        th5_1  = (const float*)d_in[5];
        th5_2  = (const float*)d_in[6];
    }

    float* out = (float*)d_out;

    dim3 g1(Bv * Ev, Nv / 256);
    proj_kernel<<<g1, 256>>>(emb, th12_1, th12_2);

    dim3 g2(Nv / TI, Bv * Ev);
    edge_kernel<<<g2, 256>>>(th5_1, th5_2, out);
}

// round 3
// speedup vs baseline: 1.2140x; 1.2140x over previous
#include <cuda_runtime.h>

#define Bv 2
#define Cv 64
#define Nv 1024
#define Ev 32
#define TI 8   // i-rows per block in edge kernel

// Scratch: PRE-DOUBLED projected node features 2*t1, 2*t2: (B*E, N) each.
__device__ float g_t1[Bv * Ev * Nv];
__device__ float g_t2[Bv * Ev * Nv];

// ---------------------------------------------------------------------------
// Kernel 1: t[b,e,n] = 2 * sum_c th12[e,c] * emb[b,c,n], both weight sets.
// (Pre-doubling folds the "m + m" of the reference into the projection.)
// ---------------------------------------------------------------------------
__global__ void proj_kernel(const float* __restrict__ emb,
                            const float* __restrict__ th12_1,
                            const float* __restrict__ th12_2) {
    const int be = blockIdx.x;          // 0..B*E-1
    const int b  = be / Ev;
    const int e  = be % Ev;
    const int n  = blockIdx.y * blockDim.x + threadIdx.x;

    __shared__ float w1[Cv];
    __shared__ float w2[Cv];
    if (threadIdx.x < Cv) {
        // fold the factor 2 into the weights
        w1[threadIdx.x] = 2.0f * th12_1[e * Cv + threadIdx.x];
        w2[threadIdx.x] = 2.0f * th12_2[e * Cv + threadIdx.x];
    }
    __syncthreads();

    const float* ebase = emb + (size_t)b * Cv * Nv + n;
    float s1 = 0.0f, s2 = 0.0f;
#pragma unroll 16
    for (int c = 0; c < Cv; ++c) {
        float x = ebase[(size_t)c * Nv];   // coalesced
        s1 = fmaf(w1[c], x, s1);
        s2 = fmaf(w2[c], x, s2);
    }
    g_t1[be * Nv + n] = s1;
    g_t2[be * Nv + n] = s2;
}

// ---------------------------------------------------------------------------
// Kernel 2: out[b,e,i,j] = relu(max(T1_i,T1_j) + a5*dij)
//                        * sigmoid(relu(max(T2_i,T2_j) + g5*dij))
// where T = 2*t (pre-doubled). Diagonal handled by a per-row predicated fix
// (only the thread owning column i), keeping the hot loop diag-free.
// sigmoid(x) = 0.5*tanh(0.5*x) + 0.5  (1 MUFU instead of 2).
// ---------------------------------------------------------------------------
__device__ __forceinline__ float tanh_approx(float x) {
    float y;
    asm("tanh.approx.f32 %0, %1;" : "=f"(y) : "f"(x));
    return y;
}

// out = relu(m1) * sigmoid(relu(m2)), m pre-activation values
__device__ __forceinline__ float edge_elem(float m1, float m2) {
    float a  = fmaxf(m1, 0.0f);
    float xr = fmaxf(m2, 0.0f);
    float h  = tanh_approx(0.5f * xr);
    float t  = 0.5f * a;
    return fmaf(t, h, t);               // 0.5*a*(h+1)
}

__global__ void __launch_bounds__(256) edge_kernel(
    const float* __restrict__ th5_1,
    const float* __restrict__ th5_2,
    float* __restrict__ out) {
    const int i0 = blockIdx.x * TI;
    const int be = blockIdx.y;
    const int e  = be % Ev;

    const float* __restrict__ r1 = g_t1 + be * Nv;
    const float* __restrict__ r2 = g_t2 + be * Nv;

    const int j0 = threadIdx.x * 4;
    const float4 tj1 = *reinterpret_cast<const float4*>(r1 + j0);
    const float4 tj2 = *reinterpret_cast<const float4*>(r2 + j0);

    float* dst = out + (((size_t)be * Nv) + i0) * Nv + j0;

#pragma unroll
    for (int r = 0; r < TI; ++r) {
        const int i = i0 + r;
        const float ti1 = r1[i];        // uniform broadcast (L2-hot)
        const float ti2 = r2[i];

        float4 o;
        o.x = edge_elem(fmaxf(ti1, tj1.x), fmaxf(ti2, tj2.x));
        o.y = edge_elem(fmaxf(ti1, tj1.y), fmaxf(ti2, tj2.y));
        o.z = edge_elem(fmaxf(ti1, tj1.z), fmaxf(ti2, tj2.z));
        o.w = edge_elem(fmaxf(ti1, tj1.w), fmaxf(ti2, tj2.w));

        // Diagonal fix: only the thread whose 4-wide slice contains column i.
        const unsigned k = (unsigned)(i - j0);
        if (k < 4u) {
            const float a5 = th5_1[e];
            const float g5 = th5_2[e];
            // at the diagonal max(Ti,Tj) == Ti
            float v = edge_elem(ti1 + a5, ti2 + g5);
            if      (k == 0u) o.x = v;
            else if (k == 1u) o.y = v;
            else if (k == 2u) o.z = v;
            else              o.w = v;
        }

        __stcs(reinterpret_cast<float4*>(dst), o);   // streaming store
        dst += Nv;
    }
}

// ---------------------------------------------------------------------------
// Launch. Resolve input indices defensively from in_sizes:
//   dict order:   sizes [BCN, EC, EC, E, EC, EC, E] -> th5 at 3 and 6
//   sorted order: sizes [BCN, EC, EC, EC, EC, E, E] -> th5 at 5 and 6
// ---------------------------------------------------------------------------
extern "C" void kernel_launch(void* const* d_in, const int* in_sizes, int n_in,
                              void* d_out, int out_size) {
    const float* emb = (const float*)d_in[0];
    const float *th12_1, *th5_1, *th12_2, *th5_2;

    if (n_in >= 7 && in_sizes[3] == Ev) {
        th12_1 = (const float*)d_in[1];
        th5_1  = (const float*)d_in[3];
        th12_2 = (const float*)d_in[4];
        th5_2  = (const float*)d_in[6];
    } else {
        th12_1 = (const float*)d_in[1];
        th12_2 = (const float*)d_in[2];
        th5_1  = (const float*)d_in[5];
        th5_2  = (const float*)d_in[6];
    }

    float* out = (float*)d_out;

    dim3 g1(Bv * Ev, Nv / 256);
    proj_kernel<<<g1, 256>>>(emb, th12_1, th12_2);

    dim3 g2(Nv / TI, Bv * Ev);
    edge_kernel<<<g2, 256>>>(th5_1, th5_2, out);
}

// round 4
// speedup vs baseline: 1.2206x; 1.0054x over previous
#include <cuda_runtime.h>

#define Bv 2
#define Cv 64
#define Nv 1024
#define Ev 32
#define TI 8                 // i-rows per block
#define PROJ_CHUNKS 4        // blocks per be that carry proj work (256 n each)

// Scratch: PRE-DOUBLED projected node features 2*t1, 2*t2: (B*E, N) each.
__device__ float g_t1[Bv * Ev * Nv];
__device__ float g_t2[Bv * Ev * Nv];
// Per-(be,chunk) ready flags. Idempotent (=1): stale-set on graph replays is a
// benign identical-value race (proj rewrites bit-identical data).
__device__ int g_flag[Bv * Ev * PROJ_CHUNKS];

__device__ __forceinline__ float tanh_approx(float x) {
    float y;
    asm("tanh.approx.f32 %0, %1;" : "=f"(y) : "f"(x));
    return y;
}

// out = relu(m1) * sigmoid(relu(m2))
__device__ __forceinline__ float edge_elem(float m1, float m2) {
    float a  = fmaxf(m1, 0.0f);
    float xr = fmaxf(m2, 0.0f);
    float h  = tanh_approx(0.5f * xr);
    float t  = 0.5f * a;
    return fmaf(t, h, t);               // 0.5*a*(h+1) == a * sigmoid(xr)
}

// ---------------------------------------------------------------------------
// Fused kernel. Grid (N/TI=128, B*E=64), block 256.
//   xc < PROJ_CHUNKS: also computes proj chunk xc of this be, publishes flag.
//   Everyone waits for this be's 4 flags, then writes TI output rows.
// Scheduling order (x-fastest linear) puts a be's proj blocks before its
// edge-only blocks -> no deadlock; first waves overlap proj with stores.
// ---------------------------------------------------------------------------
__global__ void __launch_bounds__(256) fused_kernel(
    const float* __restrict__ emb,
    const float* __restrict__ th12_1,
    const float* __restrict__ th12_2,
    const float* __restrict__ th5_1,
    const float* __restrict__ th5_2,
    float* __restrict__ out) {

    const int xc = blockIdx.x;          // 0..127
    const int be = blockIdx.y;          // 0..63
    const int b  = be / Ev;
    const int e  = be % Ev;

    // ---- producer phase (first 4 x-blocks of each be) ----
    if (xc < PROJ_CHUNKS) {
        __shared__ float w1[Cv];
        __shared__ float w2[Cv];
        if (threadIdx.x < Cv) {
            // fold the reference's "m + m" doubling into the weights
            w1[threadIdx.x] = 2.0f * th12_1[e * Cv + threadIdx.x];
            w2[threadIdx.x] = 2.0f * th12_2[e * Cv + threadIdx.x];
        }
        __syncthreads();

        const int n = xc * 256 + threadIdx.x;
        const float* ebase = emb + (size_t)b * Cv * Nv + n;
        float s1 = 0.0f, s2 = 0.0f;
#pragma unroll 16
        for (int c = 0; c < Cv; ++c) {
            float x = ebase[(size_t)c * Nv];
            s1 = fmaf(w1[c], x, s1);
            s2 = fmaf(w2[c], x, s2);
        }
        g_t1[be * Nv + n] = s1;
        g_t2[be * Nv + n] = s2;

        __threadfence();                // make t visible GPU-wide
        __syncthreads();                // all threads' stores + fences done
        if (threadIdx.x == 0) {
            *((volatile int*)&g_flag[be * PROJ_CHUNKS + xc]) = 1;
        }
    }

    // ---- wait for this be's full t rows ----
    if (threadIdx.x < PROJ_CHUNKS) {
        volatile int* f = &g_flag[be * PROJ_CHUNKS + threadIdx.x];
        while (*f == 0) { __nanosleep(64); }
    }
    __syncthreads();
    __threadfence();                    // order flag-read before t reads

    // ---- edge phase ----
    const float* __restrict__ r1 = g_t1 + be * Nv;
    const float* __restrict__ r2 = g_t2 + be * Nv;

    const int i0 = xc * TI;
    const int j0 = threadIdx.x * 4;
    const float4 tj1 = *reinterpret_cast<const float4*>(r1 + j0);
    const float4 tj2 = *reinterpret_cast<const float4*>(r2 + j0);

    float* dst = out + (((size_t)be * Nv) + i0) * Nv + j0;

#pragma unroll
    for (int r = 0; r < TI; ++r) {
        const int i = i0 + r;
        const float ti1 = r1[i];        // uniform broadcast (L2-hot)
        const float ti2 = r2[i];

        float4 o;
        o.x = edge_elem(fmaxf(ti1, tj1.x), fmaxf(ti2, tj2.x));
        o.y = edge_elem(fmaxf(ti1, tj1.y), fmaxf(ti2, tj2.y));
        o.z = edge_elem(fmaxf(ti1, tj1.z), fmaxf(ti2, tj2.z));
        o.w = edge_elem(fmaxf(ti1, tj1.w), fmaxf(ti2, tj2.w));

        // Diagonal fix: only the thread whose 4-wide slice contains column i.
        const unsigned k = (unsigned)(i - j0);
        if (k < 4u) {
            const float a5 = th5_1[e];
            const float g5 = th5_2[e];
            float v = edge_elem(ti1 + a5, ti2 + g5);  // max(Ti,Tj)==Ti on diag
            if      (k == 0u) o.x = v;
            else if (k == 1u) o.y = v;
            else if (k == 2u) o.z = v;
            else              o.w = v;
        }

        __stcs(reinterpret_cast<float4*>(dst), o);   // streaming store
        dst += Nv;
    }
}

// ---------------------------------------------------------------------------
// Launch. Resolve input indices defensively from in_sizes:
//   dict order:   sizes [BCN, EC, EC, E, EC, EC, E] -> th5 at 3 and 6
//   sorted order: sizes [BCN, EC, EC, EC, EC, E, E] -> th5 at 5 and 6
// ---------------------------------------------------------------------------
extern "C" void kernel_launch(void* const* d_in, const int* in_sizes, int n_in,
                              void* d_out, int out_size) {
    const float* emb = (const float*)d_in[0];
    const float *th12_1, *th5_1, *th12_2, *th5_2;

    if (n_in >= 7 && in_sizes[3] == Ev) {
        th12_1 = (const float*)d_in[1];
        th5_1  = (const float*)d_in[3];
        th12_2 = (const float*)d_in[4];
        th5_2  = (const float*)d_in[6];
    } else {
        th12_1 = (const float*)d_in[1];
        th12_2 = (const float*)d_in[2];
        th5_1  = (const float*)d_in[5];
        th5_2  = (const float*)d_in[6];
    }

    float* out = (float*)d_out;

    dim3 g(Nv / TI, Bv * Ev);
    fused_kernel<<<g, 256>>>(emb, th12_1, th12_2, th5_1, th5_2, out);
}

// round 5
// speedup vs baseline: 1.2669x; 1.0379x over previous
#include <cuda_runtime.h>

#define Bv 2
#define Cv 64
#define Nv 1024
#define Ev 32
#define TI 8                 // i-rows per block
#define PROJ_CHUNKS 4        // producer blocks per be (256 n each)

// Scratch: PRE-DOUBLED projected node features 2*t1, 2*t2: (B*E, N) each.
__device__ float g_t1[Bv * Ev * Nv];
__device__ float g_t2[Bv * Ev * Nv];
// Per-(be,chunk) ready flags. Idempotent (=1): stale-set on graph replays is a
// benign identical-value race (proj rewrites bit-identical data).
__device__ int g_flag[Bv * Ev * PROJ_CHUNKS];

__device__ __forceinline__ float tanh_approx(float x) {
    float y;
    asm("tanh.approx.f32 %0, %1;" : "=f"(y) : "f"(x));
    return y;
}

__device__ __forceinline__ int ld_acquire_gpu(const int* p) {
    int v;
    asm volatile("ld.acquire.gpu.global.b32 %0, [%1];" : "=r"(v) : "l"(p) : "memory");
    return v;
}

// out = relu(m1) * sigmoid(relu(m2))
__device__ __forceinline__ float edge_elem(float m1, float m2) {
    float a  = fmaxf(m1, 0.0f);
    float xr = fmaxf(m2, 0.0f);
    float h  = tanh_approx(0.5f * xr);
    float t  = 0.5f * a;
    return fmaf(t, h, t);               // 0.5*a*(h+1) == a * sigmoid(xr)
}

// ---------------------------------------------------------------------------
// Fused kernel. Grid (N/TI=128, B*E=64), block 256, forced 8 blocks/SM.
//   xc < PROJ_CHUNKS: computes proj chunk xc of this be, publishes flag
//   (release: st t -> threadfence -> flag). Everyone acquires this be's
//   4 flags, then reads t via L2 (__ldcg -> no L1-staleness, no L1 flush)
//   and writes TI output rows with streaming stores.
// ---------------------------------------------------------------------------
__global__ void __launch_bounds__(256, 8) fused_kernel(
    const float* __restrict__ emb,
    const float* __restrict__ th12_1,
    const float* __restrict__ th12_2,
    const float* __restrict__ th5_1,
    const float* __restrict__ th5_2,
    float* __restrict__ out) {

    const int xc = blockIdx.x;          // 0..127
    const int be = blockIdx.y;          // 0..63
    const int b  = be / Ev;
    const int e  = be % Ev;

    // ---- producer phase (first 4 x-blocks of each be) ----
    if (xc < PROJ_CHUNKS) {
        __shared__ float w1[Cv];
        __shared__ float w2[Cv];
        if (threadIdx.x < Cv) {
            // fold the reference's "m + m" doubling into the weights
            w1[threadIdx.x] = 2.0f * th12_1[e * Cv + threadIdx.x];
            w2[threadIdx.x] = 2.0f * th12_2[e * Cv + threadIdx.x];
        }
        __syncthreads();

        const int n = xc * 256 + threadIdx.x;
        const float* ebase = emb + (size_t)b * Cv * Nv + n;
        float s1 = 0.0f, s2 = 0.0f;
#pragma unroll 16
        for (int c = 0; c < Cv; ++c) {
            float x = ebase[(size_t)c * Nv];
            s1 = fmaf(w1[c], x, s1);
            s2 = fmaf(w2[c], x, s2);
        }
        g_t1[be * Nv + n] = s1;
        g_t2[be * Nv + n] = s2;

        __threadfence();                // release: t visible before flag
        __syncthreads();
        if (threadIdx.x == 0) {
            *((volatile int*)&g_flag[be * PROJ_CHUNKS + xc]) = 1;
        }
    }

    // ---- acquire this be's full t rows (no L1 flush; t read via L2) ----
    if (threadIdx.x < PROJ_CHUNKS) {
        const int* f = &g_flag[be * PROJ_CHUNKS + threadIdx.x];
        while (ld_acquire_gpu(f) == 0) { __nanosleep(64); }
    }
    __syncthreads();

    // ---- edge phase ----
    const float* __restrict__ r1 = g_t1 + be * Nv;
    const float* __restrict__ r2 = g_t2 + be * Nv;

    const int i0 = xc * TI;
    const int j0 = threadIdx.x * 4;
    const float4 tj1 = __ldcg(reinterpret_cast<const float4*>(r1 + j0));
    const float4 tj2 = __ldcg(reinterpret_cast<const float4*>(r2 + j0));

    float* dst = out + (((size_t)be * Nv) + i0) * Nv + j0;

#pragma unroll
    for (int r = 0; r < TI; ++r) {
        const int i = i0 + r;
        const float ti1 = __ldcg(r1 + i);   // uniform broadcast (L2-hot)
        const float ti2 = __ldcg(r2 + i);

        float4 o;
        o.x = edge_elem(fmaxf(ti1, tj1.x), fmaxf(ti2, tj2.x));
        o.y = edge_elem(fmaxf(ti1, tj1.y), fmaxf(ti2, tj2.y));
        o.z = edge_elem(fmaxf(ti1, tj1.z), fmaxf(ti2, tj2.z));
        o.w = edge_elem(fmaxf(ti1, tj1.w), fmaxf(ti2, tj2.w));

        // Diagonal fix: only the thread whose 4-wide slice contains column i.
        const unsigned k = (unsigned)(i - j0);
        if (k < 4u) {
            const float a5 = th5_1[e];
            const float g5 = th5_2[e];
            float v = edge_elem(ti1 + a5, ti2 + g5);  // max(Ti,Tj)==Ti on diag
            if      (k == 0u) o.x = v;
            else if (k == 1u) o.y = v;
            else if (k == 2u) o.z = v;
            else              o.w = v;
        }

        __stcs(reinterpret_cast<float4*>(dst), o);   // streaming store
        dst += Nv;
    }
}

// ---------------------------------------------------------------------------
// Launch. Resolve input indices defensively from in_sizes:
//   dict order:   sizes [BCN, EC, EC, E, EC, EC, E] -> th5 at 3 and 6
//   sorted order: sizes [BCN, EC, EC, EC, EC, E, E] -> th5 at 5 and 6
// ---------------------------------------------------------------------------
extern "C" void kernel_launch(void* const* d_in, const int* in_sizes, int n_in,
                              void* d_out, int out_size) {
    const float* emb = (const float*)d_in[0];
    const float *th12_1, *th5_1, *th12_2, *th5_2;

    if (n_in >= 7 && in_sizes[3] == Ev) {
        th12_1 = (const float*)d_in[1];
        th5_1  = (const float*)d_in[3];
        th12_2 = (const float*)d_in[4];
        th5_2  = (const float*)d_in[6];
    } else {
        th12_1 = (const float*)d_in[1];
        th12_2 = (const float*)d_in[2];
        th5_1  = (const float*)d_in[5];
        th5_2  = (const float*)d_in[6];
    }

    float* out = (float*)d_out;

    dim3 g(Nv / TI, Bv * Ev);
    fused_kernel<<<g, 256>>>(emb, th12_1, th12_2, th5_1, th5_2, out);
}

// round 6
// speedup vs baseline: 1.3274x; 1.0478x over previous
#include <cuda_runtime.h>

#define Bv 2
#define Cv 64
#define Nv 1024
#define Ev 32
#define TI 8                 // i-rows per edge block
#define PROJ_CHUNKS 4        // producer blocks per be (256 n each)
#define NPROD (Bv * Ev * PROJ_CHUNKS)        // 256 producer blocks
#define NEDGE (Bv * Ev * (Nv / TI))          // 8192 edge blocks

// Scratch: PRE-DOUBLED projected node features 2*t1, 2*t2: (B*E, N) each.
__device__ float g_t1[Bv * Ev * Nv];
__device__ float g_t2[Bv * Ev * Nv];
// Per-(be,chunk) ready flags. Idempotent (=1): stale-set on graph replays is a
// benign identical-value race (proj rewrites bit-identical data).
__device__ int g_flag[NPROD];

__device__ __forceinline__ float tanh_approx(float x) {
    float y;
    asm("tanh.approx.f32 %0, %1;" : "=f"(y) : "f"(x));
    return y;
}

__device__ __forceinline__ int ld_acquire_gpu(const int* p) {
    int v;
    asm volatile("ld.acquire.gpu.global.b32 %0, [%1];" : "=r"(v) : "l"(p) : "memory");
    return v;
}

// out = relu(m1) * sigmoid(relu(m2))
__device__ __forceinline__ float edge_elem(float m1, float m2) {
    float a  = fmaxf(m1, 0.0f);
    float xr = fmaxf(m2, 0.0f);
    float h  = tanh_approx(0.5f * xr);
    float t  = 0.5f * a;
    return fmaf(t, h, t);               // 0.5*a*(h+1) == a * sigmoid(xr)
}

// ---------------------------------------------------------------------------
// Fused kernel, 1-D grid of NPROD + NEDGE blocks.
//   bid <  NPROD : pure producer — proj chunk (be = bid/4, chunk = bid%4),
//                  release (st t -> threadfence -> flag=1), exit.
//   bid >= NPROD : pure consumer — acquire its be's 4 flags, read t via L2
//                  (__ldcg; no L1-staleness concern), write TI output rows.
// ALL producers land in wave 1, so only wave-1 consumers ever spin (~2-3us);
// every later wave streams with flags already set.
// ---------------------------------------------------------------------------
__global__ void __launch_bounds__(256, 8) fused_kernel(
    const float* __restrict__ emb,
    const float* __restrict__ th12_1,
    const float* __restrict__ th12_2,
    const float* __restrict__ th5_1,
    const float* __restrict__ th5_2,
    float* __restrict__ out) {

    const int bid = blockIdx.x;

    if (bid < NPROD) {
        // ---- producer ----
        const int be = bid >> 2;            // 0..63
        const int xc = bid & 3;             // chunk 0..3
        const int b  = be / Ev;
        const int e  = be % Ev;

        __shared__ float w1[Cv];
        __shared__ float w2[Cv];
        if (threadIdx.x < Cv) {
            // fold the reference's "m + m" doubling into the weights
            w1[threadIdx.x] = 2.0f * th12_1[e * Cv + threadIdx.x];
            w2[threadIdx.x] = 2.0f * th12_2[e * Cv + threadIdx.x];
        }
        __syncthreads();

        const int n = xc * 256 + threadIdx.x;
        const float* ebase = emb + (size_t)b * Cv * Nv + n;
        float s1 = 0.0f, s2 = 0.0f;
#pragma unroll 16
        for (int c = 0; c < Cv; ++c) {
            float x = ebase[(size_t)c * Nv];
            s1 = fmaf(w1[c], x, s1);
            s2 = fmaf(w2[c], x, s2);
        }
        g_t1[be * Nv + n] = s1;
        g_t2[be * Nv + n] = s2;

        __threadfence();                    // release: t visible before flag
        __syncthreads();
        if (threadIdx.x == 0) {
            *((volatile int*)&g_flag[bid]) = 1;
        }
        return;
    }

    // ---- consumer (edge) ----
    const int eid = bid - NPROD;
    const int be  = eid >> 7;               // 0..63 (be-major: contiguous sweep)
    const int xc  = eid & 127;              // 0..127
    const int e   = be % Ev;

    if (threadIdx.x < PROJ_CHUNKS) {
        const int* f = &g_flag[be * PROJ_CHUNKS + threadIdx.x];
        while (ld_acquire_gpu(f) == 0) { __nanosleep(64); }
    }
    __syncthreads();

    const float* __restrict__ r1 = g_t1 + be * Nv;
    const float* __restrict__ r2 = g_t2 + be * Nv;

    const int i0 = xc * TI;
    const int j0 = threadIdx.x * 4;
    const float4 tj1 = __ldcg(reinterpret_cast<const float4*>(r1 + j0));
    const float4 tj2 = __ldcg(reinterpret_cast<const float4*>(r2 + j0));

    float* dst = out + (((size_t)be * Nv) + i0) * Nv + j0;

#pragma unroll
    for (int r = 0; r < TI; ++r) {
        const int i = i0 + r;
        const float ti1 = __ldcg(r1 + i);   // uniform broadcast (L2-hot)
        const float ti2 = __ldcg(r2 + i);

        float4 o;
        o.x = edge_elem(fmaxf(ti1, tj1.x), fmaxf(ti2, tj2.x));
        o.y = edge_elem(fmaxf(ti1, tj1.y), fmaxf(ti2, tj2.y));
        o.z = edge_elem(fmaxf(ti1, tj1.z), fmaxf(ti2, tj2.z));
        o.w = edge_elem(fmaxf(ti1, tj1.w), fmaxf(ti2, tj2.w));

        // Diagonal fix: only the thread whose 4-wide slice contains column i.
        const unsigned k = (unsigned)(i - j0);
        if (k < 4u) {
            const float a5 = th5_1[e];
            const float g5 = th5_2[e];
            float v = edge_elem(ti1 + a5, ti2 + g5);  // max(Ti,Tj)==Ti on diag
            if      (k == 0u) o.x = v;
            else if (k == 1u) o.y = v;
            else if (k == 2u) o.z = v;
            else              o.w = v;
        }

        __stcs(reinterpret_cast<float4*>(dst), o);   // streaming store
        dst += Nv;
    }
}

// ---------------------------------------------------------------------------
// Launch. Resolve input indices defensively from in_sizes:
//   dict order:   sizes [BCN, EC, EC, E, EC, EC, E] -> th5 at 3 and 6
//   sorted order: sizes [BCN, EC, EC, EC, EC, E, E] -> th5 at 5 and 6
// ---------------------------------------------------------------------------
extern "C" void kernel_launch(void* const* d_in, const int* in_sizes, int n_in,
                              void* d_out, int out_size) {
    const float* emb = (const float*)d_in[0];
    const float *th12_1, *th5_1, *th12_2, *th5_2;

    if (n_in >= 7 && in_sizes[3] == Ev) {
        th12_1 = (const float*)d_in[1];
        th5_1  = (const float*)d_in[3];
        th12_2 = (const float*)d_in[4];
        th5_2  = (const float*)d_in[6];
    } else {
        th12_1 = (const float*)d_in[1];
        th12_2 = (const float*)d_in[2];
        th5_1  = (const float*)d_in[5];
        th5_2  = (const float*)d_in[6];
    }

    float* out = (float*)d_out;

    fused_kernel<<<NPROD + NEDGE, 256>>>(emb, th12_1, th12_2, th5_1, th5_2, out);
}